// round 1
// baseline (speedup 1.0000x reference)
#include <cuda_runtime.h>
#include <math.h>

// Problem constants (max sizes; actual sizes taken from in_sizes)
#define MAXF 200000

// Accumulator layout (SoA slices inside one big device buffer):
//   [0,3F)    : sum of f_atom per frag (x,y,z interleaved as 3 arrays of F)
//   [3F,4F)   : count
//   [4F,7F)   : torque
//   [7F,13F)  : rr sums: xx, yy, zz, xy, xz, yz
__device__ float g_acc[13 * MAXF];

__global__ void zero_acc_kernel(int total) {
    int i = blockIdx.x * blockDim.x + threadIdx.x;
    int stride = gridDim.x * blockDim.x;
    for (; i < total; i += stride) g_acc[i] = 0.0f;
}

__global__ void scatter_kernel(const float* __restrict__ f_atom,
                               const float* __restrict__ atom_pos,
                               const float* __restrict__ T_frag,
                               const int*   __restrict__ frag_id,
                               int N, int F) {
    int i = blockIdx.x * blockDim.x + threadIdx.x;
    if (i >= N) return;

    int fid = frag_id[i];

    float fx = f_atom[3 * i + 0];
    float fy = f_atom[3 * i + 1];
    float fz = f_atom[3 * i + 2];

    float rx = atom_pos[3 * i + 0] - __ldg(&T_frag[3 * fid + 0]);
    float ry = atom_pos[3 * i + 1] - __ldg(&T_frag[3 * fid + 1]);
    float rz = atom_pos[3 * i + 2] - __ldg(&T_frag[3 * fid + 2]);

    // torque = r x f
    float tx = ry * fz - rz * fy;
    float ty = rz * fx - rx * fz;
    float tz = rx * fy - ry * fx;

    float* sumx = g_acc;
    float* cnt  = g_acc + 3 * F;
    float* tq   = g_acc + 4 * F;
    float* rr   = g_acc + 7 * F;

    atomicAdd(&sumx[fid],         fx);
    atomicAdd(&sumx[F + fid],     fy);
    atomicAdd(&sumx[2 * F + fid], fz);
    atomicAdd(&cnt[fid],          1.0f);
    atomicAdd(&tq[fid],           tx);
    atomicAdd(&tq[F + fid],       ty);
    atomicAdd(&tq[2 * F + fid],   tz);
    atomicAdd(&rr[fid],           rx * rx);
    atomicAdd(&rr[F + fid],       ry * ry);
    atomicAdd(&rr[2 * F + fid],   rz * rz);
    atomicAdd(&rr[3 * F + fid],   rx * ry);
    atomicAdd(&rr[4 * F + fid],   rx * rz);
    atomicAdd(&rr[5 * F + fid],   ry * rz);
}

// Jacobi eigensolver for symmetric 3x3. A is full-stored (both triangles),
// destroyed to diagonal. V accumulates eigenvectors as COLUMNS (A = V D V^T).
__device__ __forceinline__ void jacobi3(float A[3][3], float V[3][3]) {
    V[0][0] = 1.f; V[0][1] = 0.f; V[0][2] = 0.f;
    V[1][0] = 0.f; V[1][1] = 1.f; V[1][2] = 0.f;
    V[2][0] = 0.f; V[2][1] = 0.f; V[2][2] = 1.f;

    #pragma unroll 1
    for (int sweep = 0; sweep < 8; sweep++) {
        #pragma unroll
        for (int k = 0; k < 3; k++) {
            const int p = (k == 2) ? 1 : 0;
            const int q = (k == 0) ? 1 : 2;
            const int r = 3 - p - q;
            float apq = A[p][q];
            float scale = fabsf(A[p][p]) + fabsf(A[q][q]);
            if (fabsf(apq) <= 1e-12f * scale + 1e-30f) continue;

            float theta = (A[q][q] - A[p][p]) / (2.0f * apq);
            float t = copysignf(1.0f, theta) / (fabsf(theta) + sqrtf(theta * theta + 1.0f));
            float c = rsqrtf(t * t + 1.0f);
            float s = t * c;

            float app = A[p][p] - t * apq;
            float aqq = A[q][q] + t * apq;
            float arp = A[r][p];
            float arq = A[r][q];

            A[p][p] = app;
            A[q][q] = aqq;
            A[p][q] = 0.f; A[q][p] = 0.f;
            float nrp = c * arp - s * arq;
            float nrq = s * arp + c * arq;
            A[r][p] = nrp; A[p][r] = nrp;
            A[r][q] = nrq; A[q][r] = nrq;

            #pragma unroll
            for (int i = 0; i < 3; i++) {
                float vip = V[i][p];
                float viq = V[i][q];
                V[i][p] = c * vip - s * viq;
                V[i][q] = s * vip + c * viq;
            }
        }
    }
}

__global__ void frag_kernel(const int* __restrict__ frag_sizes,
                            float* __restrict__ out, int F) {
    int f = blockIdx.x * blockDim.x + threadIdx.x;
    if (f >= F) return;

    const float* sumx = g_acc;
    const float* cnt  = g_acc + 3 * F;
    const float* tq   = g_acc + 4 * F;
    const float* rr   = g_acc + 7 * F;

    float c   = cnt[f];
    float den = fmaxf(c, 1.0f);
    float vx = sumx[f] / den;
    float vy = sumx[F + f] / den;
    float vz = sumx[2 * F + f] / den;

    float tx = tq[f];
    float ty = tq[F + f];
    float tz = tq[2 * F + f];

    float sxx = rr[f];
    float syy = rr[F + f];
    float szz = rr[2 * F + f];
    float sxy = rr[3 * F + f];
    float sxz = rr[4 * F + f];
    float syz = rr[5 * F + f];

    // I = tr(S) * eye - S,  S = sum r r^T
    float A[3][3];
    A[0][0] = syy + szz;  A[1][1] = sxx + szz;  A[2][2] = sxx + syy;
    A[0][1] = -sxy; A[1][0] = -sxy;
    A[0][2] = -sxz; A[2][0] = -sxz;
    A[1][2] = -syz; A[2][1] = -syz;

    float V[3][3];
    jacobi3(A, V);
    float w[3] = {A[0][0], A[1][1], A[2][2]};

    float maxe = fmaxf(fmaxf(w[0], w[1]), w[2]);
    maxe = fmaxf(maxe, 1e-8f);

    int fs = frag_sizes[f];
    float obs[3];
    #pragma unroll
    for (int i = 0; i < 3; i++)
        obs[i] = (w[i] > 0.01f * maxe) ? 1.0f : 0.0f;
    if (fs <= 1) { obs[0] = 0.f; obs[1] = 0.f; obs[2] = 0.f; }

    // t_eig = V^T * torque ; scale_i = obs_i / max(w_i, 1e-6)
    float coef[3];
    #pragma unroll
    for (int i = 0; i < 3; i++) {
        float te = V[0][i] * tx + V[1][i] * ty + V[2][i] * tz;
        coef[i] = te / fmaxf(w[i], 1e-6f) * obs[i];
    }

    float om[3];
    #pragma unroll
    for (int j = 0; j < 3; j++)
        om[j] = V[j][0] * coef[0] + V[j][1] * coef[1] + V[j][2] * coef[2];

    // P = V diag(obs) V^T
    float P[3][3];
    #pragma unroll
    for (int j = 0; j < 3; j++)
        #pragma unroll
        for (int k2 = 0; k2 < 3; k2++)
            P[j][k2] = V[j][0] * obs[0] * V[k2][0]
                     + V[j][1] * obs[1] * V[k2][1]
                     + V[j][2] * obs[2] * V[k2][2];

    // Output layout: [v_frag F*3][omega F*3][P F*9]
    out[3 * f + 0] = vx;
    out[3 * f + 1] = vy;
    out[3 * f + 2] = vz;

    float* o_om = out + 3 * F;
    o_om[3 * f + 0] = om[0];
    o_om[3 * f + 1] = om[1];
    o_om[3 * f + 2] = om[2];

    float* o_P = out + 6 * F;
    #pragma unroll
    for (int j = 0; j < 3; j++)
        #pragma unroll
        for (int k2 = 0; k2 < 3; k2++)
            o_P[9 * f + 3 * j + k2] = P[j][k2];
}

extern "C" void kernel_launch(void* const* d_in, const int* in_sizes, int n_in,
                              void* d_out, int out_size) {
    const float* f_atom     = (const float*)d_in[0];
    const float* atom_pos   = (const float*)d_in[1];
    const float* T_frag     = (const float*)d_in[2];
    const int*   frag_id    = (const int*)d_in[3];
    const int*   frag_sizes = (const int*)d_in[4];

    int N = in_sizes[0] / 3;
    int F = in_sizes[2] / 3;

    float* out = (float*)d_out;

    zero_acc_kernel<<<1024, 256>>>(13 * F);
    scatter_kernel<<<(N + 255) / 256, 256>>>(f_atom, atom_pos, T_frag, frag_id, N, F);
    frag_kernel<<<(F + 127) / 128, 128>>>(frag_sizes, out, F);
}

// round 2
// speedup vs baseline: 2.5888x; 2.5888x over previous
#include <cuda_runtime.h>
#include <math.h>

#define MAXF 200000

// Per-fragment accumulator: 16 floats, 64B-aligned.
//  0: sum fx   1: sum fy   2: sum fz   3: count
//  4: sum px   5: sum py   6: sum pz   7: sum (p x f).x
//  8: (pxf).y  9: (pxf).z 10: sum pxx 11: sum pyy
// 12: sum pzz 13: sum pxy 14: sum pxz 15: sum pyz
__device__ __align__(16) float g_acc[16 * MAXF];

__global__ void zero_acc_kernel(int total4) {
    int i = blockIdx.x * blockDim.x + threadIdx.x;
    int stride = gridDim.x * blockDim.x;
    float4* p = reinterpret_cast<float4*>(g_acc);
    float4 z = make_float4(0.f, 0.f, 0.f, 0.f);
    for (; i < total4; i += stride) p[i] = z;
}

__device__ __forceinline__ void red_v4(float* addr, float a, float b, float c, float d) {
    asm volatile("red.global.add.v4.f32 [%0], {%1,%2,%3,%4};"
                 :: "l"(addr), "f"(a), "f"(b), "f"(c), "f"(d) : "memory");
}

__global__ void scatter_kernel(const float* __restrict__ f_atom,
                               const float* __restrict__ atom_pos,
                               const int*   __restrict__ frag_id,
                               int N) {
    int i = blockIdx.x * blockDim.x + threadIdx.x;
    if (i >= N) return;

    int fid = frag_id[i];

    float fx = f_atom[3 * i + 0];
    float fy = f_atom[3 * i + 1];
    float fz = f_atom[3 * i + 2];
    float px = atom_pos[3 * i + 0];
    float py = atom_pos[3 * i + 1];
    float pz = atom_pos[3 * i + 2];

    // p x f
    float cx = py * fz - pz * fy;
    float cy = pz * fx - px * fz;
    float cz = px * fy - py * fx;

    float* base = g_acc + (size_t)fid * 16;
    red_v4(base +  0, fx, fy, fz, 1.0f);
    red_v4(base +  4, px, py, pz, cx);
    red_v4(base +  8, cy, cz, px * px, py * py);
    red_v4(base + 12, pz * pz, px * py, px * pz, py * pz);
}

// Jacobi eigensolver for symmetric 3x3. A destroyed to diagonal.
// V holds eigenvectors as COLUMNS (A = V D V^T).
__device__ __forceinline__ void jacobi3(float A[3][3], float V[3][3]) {
    V[0][0] = 1.f; V[0][1] = 0.f; V[0][2] = 0.f;
    V[1][0] = 0.f; V[1][1] = 1.f; V[1][2] = 0.f;
    V[2][0] = 0.f; V[2][1] = 0.f; V[2][2] = 1.f;

    #pragma unroll 1
    for (int sweep = 0; sweep < 8; sweep++) {
        #pragma unroll
        for (int k = 0; k < 3; k++) {
            const int p = (k == 2) ? 1 : 0;
            const int q = (k == 0) ? 1 : 2;
            const int r = 3 - p - q;
            float apq = A[p][q];
            float scale = fabsf(A[p][p]) + fabsf(A[q][q]);
            if (fabsf(apq) <= 1e-12f * scale + 1e-30f) continue;

            float theta = (A[q][q] - A[p][p]) / (2.0f * apq);
            float t = copysignf(1.0f, theta) / (fabsf(theta) + sqrtf(theta * theta + 1.0f));
            float c = rsqrtf(t * t + 1.0f);
            float s = t * c;

            float app = A[p][p] - t * apq;
            float aqq = A[q][q] + t * apq;
            float arp = A[r][p];
            float arq = A[r][q];

            A[p][p] = app;
            A[q][q] = aqq;
            A[p][q] = 0.f; A[q][p] = 0.f;
            float nrp = c * arp - s * arq;
            float nrq = s * arp + c * arq;
            A[r][p] = nrp; A[p][r] = nrp;
            A[r][q] = nrq; A[q][r] = nrq;

            #pragma unroll
            for (int i = 0; i < 3; i++) {
                float vip = V[i][p];
                float viq = V[i][q];
                V[i][p] = c * vip - s * viq;
                V[i][q] = s * vip + c * viq;
            }
        }
    }
}

__global__ void frag_kernel(const float* __restrict__ T_frag,
                            const int*   __restrict__ frag_sizes,
                            float* __restrict__ out, int F) {
    int f = blockIdx.x * blockDim.x + threadIdx.x;
    if (f >= F) return;

    const float4* acc4 = reinterpret_cast<const float4*>(g_acc) + (size_t)f * 4;
    float4 a0 = acc4[0];
    float4 a1 = acc4[1];
    float4 a2 = acc4[2];
    float4 a3 = acc4[3];

    float sfx = a0.x, sfy = a0.y, sfz = a0.z, n = a0.w;
    float spx = a1.x, spy = a1.y, spz = a1.z;
    float crx = a1.w, cry = a2.x, crz = a2.y;
    float sxx = a2.z, syy = a2.w, szz = a3.x;
    float sxy = a3.y, sxz = a3.z, syz = a3.w;

    float Tx = T_frag[3 * f + 0];
    float Ty = T_frag[3 * f + 1];
    float Tz = T_frag[3 * f + 2];

    // v_frag = sum f / max(count,1)
    float den = fmaxf(n, 1.0f);
    float vx = sfx / den, vy = sfy / den, vz = sfz / den;

    // torque = sum(p x f) - T x (sum f)
    float tx = crx - (Ty * sfz - Tz * sfy);
    float ty = cry - (Tz * sfx - Tx * sfz);
    float tz = crz - (Tx * sfy - Ty * sfx);

    // Centered second moments: S_ab = sum p_a p_b - T_a sum p_b - T_b sum p_a + n T_a T_b
    float Sxx = sxx - 2.f * Tx * spx + n * Tx * Tx;
    float Syy = syy - 2.f * Ty * spy + n * Ty * Ty;
    float Szz = szz - 2.f * Tz * spz + n * Tz * Tz;
    float Sxy = sxy - Tx * spy - Ty * spx + n * Tx * Ty;
    float Sxz = sxz - Tx * spz - Tz * spx + n * Tx * Tz;
    float Syz = syz - Ty * spz - Tz * spy + n * Ty * Tz;

    // I = tr(S) * eye - S
    float A[3][3];
    A[0][0] = Syy + Szz;  A[1][1] = Sxx + Szz;  A[2][2] = Sxx + Syy;
    A[0][1] = -Sxy; A[1][0] = -Sxy;
    A[0][2] = -Sxz; A[2][0] = -Sxz;
    A[1][2] = -Syz; A[2][1] = -Syz;

    float V[3][3];
    jacobi3(A, V);
    float w[3] = {A[0][0], A[1][1], A[2][2]};

    float maxe = fmaxf(fmaxf(w[0], w[1]), w[2]);
    maxe = fmaxf(maxe, 1e-8f);

    int fs = frag_sizes[f];
    float obs[3];
    #pragma unroll
    for (int i = 0; i < 3; i++)
        obs[i] = (w[i] > 0.01f * maxe) ? 1.0f : 0.0f;
    if (fs <= 1) { obs[0] = 0.f; obs[1] = 0.f; obs[2] = 0.f; }

    float coef[3];
    #pragma unroll
    for (int i = 0; i < 3; i++) {
        float te = V[0][i] * tx + V[1][i] * ty + V[2][i] * tz;
        coef[i] = te / fmaxf(w[i], 1e-6f) * obs[i];
    }

    float om[3];
    #pragma unroll
    for (int j = 0; j < 3; j++)
        om[j] = V[j][0] * coef[0] + V[j][1] * coef[1] + V[j][2] * coef[2];

    float P[3][3];
    #pragma unroll
    for (int j = 0; j < 3; j++)
        #pragma unroll
        for (int k2 = 0; k2 < 3; k2++)
            P[j][k2] = V[j][0] * obs[0] * V[k2][0]
                     + V[j][1] * obs[1] * V[k2][1]
                     + V[j][2] * obs[2] * V[k2][2];

    out[3 * f + 0] = vx;
    out[3 * f + 1] = vy;
    out[3 * f + 2] = vz;

    float* o_om = out + 3 * F;
    o_om[3 * f + 0] = om[0];
    o_om[3 * f + 1] = om[1];
    o_om[3 * f + 2] = om[2];

    float* o_P = out + 6 * F;
    #pragma unroll
    for (int j = 0; j < 3; j++)
        #pragma unroll
        for (int k2 = 0; k2 < 3; k2++)
            o_P[9 * f + 3 * j + k2] = P[j][k2];
}

extern "C" void kernel_launch(void* const* d_in, const int* in_sizes, int n_in,
                              void* d_out, int out_size) {
    const float* f_atom     = (const float*)d_in[0];
    const float* atom_pos   = (const float*)d_in[1];
    const float* T_frag     = (const float*)d_in[2];
    const int*   frag_id    = (const int*)d_in[3];
    const int*   frag_sizes = (const int*)d_in[4];

    int N = in_sizes[0] / 3;
    int F = in_sizes[2] / 3;

    float* out = (float*)d_out;

    zero_acc_kernel<<<512, 256>>>(4 * F);          // 4 float4 per frag
    scatter_kernel<<<(N + 255) / 256, 256>>>(f_atom, atom_pos, frag_id, N);
    frag_kernel<<<(F + 127) / 128, 128>>>(T_frag, frag_sizes, out, F);
}